// round 2
// baseline (speedup 1.0000x reference)
#include <cuda_runtime.h>
#include <cuda_bf16.h>
#include <stdint.h>

#define T 4096
#define D 2048
#define E 8

// ---------------- scratch (no allocations allowed) ----------------
__device__ int   g_top_e[T * 2];     // per token: top-2 expert indices
__device__ float g_top_g[T * 2];     // per token: top-2 gate values
__device__ int   g_row_token[E * T]; // inverse map: output row -> token (== tags)
__device__ float g_row_scale[E * T]; // per output row: gate scale
__device__ int   g_loads[E];

// ---------------- kernel 1: logits + softmax + top2 ----------------
// grid = T/8 blocks, 256 threads (8 warps). warp w handles token blockIdx*8+w.
// Wg staged transposed into smem in 4 chunks of 512 d-values.
__global__ void k_logits(const float* __restrict__ x, const float* __restrict__ Wg) {
    __shared__ float sW[8][516];   // +4 pad: conflict-free writes, 16B-aligned rows
    const int warp = threadIdx.x >> 5;
    const int lane = threadIdx.x & 31;
    const int t = blockIdx.x * 8 + warp;

    double acc[E];
#pragma unroll
    for (int e = 0; e < E; e++) acc[e] = 0.0;

    for (int c = 0; c < 4; c++) {
        __syncthreads();
        // load 512 rows of Wg (each 8 floats), store transposed
        for (int i = threadIdx.x; i < 512 * 8; i += 256) {
            int d = i >> 3, e = i & 7;
            sW[e][d] = Wg[(c * 512 + d) * 8 + e];
        }
        __syncthreads();

        const float4* xr = (const float4*)(x + (size_t)t * D + c * 512);
#pragma unroll
        for (int i = 0; i < 4; i++) {
            float4 xv = xr[i * 32 + lane];
#pragma unroll
            for (int e = 0; e < E; e++) {
                float4 wv = *(const float4*)&sW[e][(i * 32 + lane) * 4];
                acc[e] += (double)xv.x * (double)wv.x;
                acc[e] += (double)xv.y * (double)wv.y;
                acc[e] += (double)xv.z * (double)wv.z;
                acc[e] += (double)xv.w * (double)wv.w;
            }
        }
    }

    // warp reduction of 8 accumulators
#pragma unroll
    for (int e = 0; e < E; e++) {
#pragma unroll
        for (int off = 16; off > 0; off >>= 1)
            acc[e] += __shfl_down_sync(0xffffffffu, acc[e], off);
    }

    if (lane == 0) {
        float lg[E];
#pragma unroll
        for (int e = 0; e < E; e++) lg[e] = (float)acc[e];

        float mx = lg[0];
#pragma unroll
        for (int e = 1; e < E; e++) mx = fmaxf(mx, lg[e]);
        float ex[E], sum = 0.f;
#pragma unroll
        for (int e = 0; e < E; e++) { ex[e] = __expf(lg[e] - mx); sum += ex[e]; }
        float inv = 1.0f / sum;

        // top-2 on logits (same order as gates); ascending scan + strict '>'
        // => lowest index wins ties, matching jax.lax.top_k
        int b0 = 0;
#pragma unroll
        for (int e = 1; e < E; e++) if (lg[e] > lg[b0]) b0 = e;
        int b1 = -1;
#pragma unroll
        for (int e = 0; e < E; e++) {
            if (e == b0) continue;
            if (b1 < 0 || lg[e] > lg[b1]) b1 = e;
        }
        g_top_e[t * 2 + 0] = b0;
        g_top_e[t * 2 + 1] = b1;
        g_top_g[t * 2 + 0] = ex[b0] * inv;
        g_top_g[t * 2 + 1] = ex[b1] * inv;
    }
}

// ---------------- kernel 2: ordered per-expert compaction ----------------
// single block, 512 threads, 8 tokens per thread (contiguous => token order)
__global__ void k_route() {
    const int NT = 512, TPB = T / NT;  // 8
    const int tid = threadIdx.x;
    const int lane = tid & 31, wid = tid >> 5;  // 16 warps
    __shared__ int wsum[16];

    // init inverse map to -1 (rows with no token)
    for (int i = tid; i < E * T; i += NT) g_row_token[i] = -1;

    int e0[TPB], e1[TPB];
    float q0[TPB], q1[TPB];
    const int t0 = tid * TPB;
#pragma unroll
    for (int j = 0; j < TPB; j++) {
        e0[j] = g_top_e[(t0 + j) * 2 + 0];
        e1[j] = g_top_e[(t0 + j) * 2 + 1];
        q0[j] = g_top_g[(t0 + j) * 2 + 0];
        q1[j] = g_top_g[(t0 + j) * 2 + 1];
    }
    __syncthreads();

    for (int e = 0; e < E; e++) {
        int cnt = 0;
#pragma unroll
        for (int j = 0; j < TPB; j++) cnt += (e0[j] == e) + (e1[j] == e);

        // warp inclusive scan
        int incl = cnt;
#pragma unroll
        for (int off = 1; off < 32; off <<= 1) {
            int v = __shfl_up_sync(0xffffffffu, incl, off);
            if (lane >= off) incl += v;
        }
        if (lane == 31) wsum[wid] = incl;
        __syncthreads();
        if (tid < 32) {
            int v = (tid < 16) ? wsum[tid] : 0;
#pragma unroll
            for (int off = 1; off < 16; off <<= 1) {
                int u = __shfl_up_sync(0xffffffffu, v, off);
                if (lane >= off) v += u;
            }
            if (tid < 16) wsum[tid] = v;
        }
        __syncthreads();

        int wbase = wid ? wsum[wid - 1] : 0;
        int p = wbase + incl - cnt;   // exclusive prefix for this thread
#pragma unroll
        for (int j = 0; j < TPB; j++) {
            if (e0[j] == e) {
                g_row_token[e * T + p] = t0 + j;
                g_row_scale[e * T + p] = q0[j];
                p++;
            } else if (e1[j] == e) {
                g_row_token[e * T + p] = t0 + j;
                g_row_scale[e * T + p] = q1[j];
                p++;
            }
        }
        if (tid == 0) g_loads[e] = wsum[15];
        __syncthreads();  // before wsum reuse
    }
}

// ---------------- kernel 3: write out_data rows ----------------
// grid = E*T blocks, 256 threads; one 2048-float row per block
__global__ void k_fill(const float* __restrict__ x, float* __restrict__ out) {
    const int row = blockIdx.x;
    const int t = g_row_token[row];
    float4* o = (float4*)(out + (size_t)row * D);
    const int i = threadIdx.x;     // 512 float4 per row, 2 per thread
    if (t < 0) {
        float4 z = make_float4(0.f, 0.f, 0.f, 0.f);
        o[i] = z;
        o[i + 256] = z;
    } else {
        const float s = g_row_scale[row];
        const float4* xr = (const float4*)(x + (size_t)t * D);
        float4 a = xr[i];
        float4 b = xr[i + 256];
        a.x *= s; a.y *= s; a.z *= s; a.w *= s;
        b.x *= s; b.y *= s; b.z *= s; b.w *= s;
        o[i] = a;
        o[i + 256] = b;
    }
}

// ---------------- kernel 4: tags + loads (as float) ----------------
__global__ void k_tail(float* __restrict__ out) {
    const int i = blockIdx.x * blockDim.x + threadIdx.x;
    const size_t base = (size_t)E * T * D;
    if (i < E * T) out[base + i] = (float)g_row_token[i];
    if (i < E) out[base + (size_t)E * T + i] = (float)g_loads[i];
}

// ---------------- launch ----------------
extern "C" void kernel_launch(void* const* d_in, const int* in_sizes, int n_in,
                              void* d_out, int out_size) {
    const float* x  = (const float*)d_in[0];
    const float* Wg = (const float*)d_in[1];
    float* out = (float*)d_out;

    k_logits<<<T / 8, 256>>>(x, Wg);
    k_route<<<1, 512>>>();
    k_fill<<<E * T, 256>>>(x, out);
    k_tail<<<(E * T + 255) / 256, 256>>>(out);
}

// round 3
// speedup vs baseline: 1.0579x; 1.0579x over previous
#include <cuda_runtime.h>
#include <cuda_bf16.h>
#include <stdint.h>

#define T 4096
#define D 2048
#define E 8

#define ZB    1024              // zero blocks in fused kernel
#define LB    (T / 8)           // logit blocks (512)
#define DATA  ((size_t)E * T * D)       // 64M floats
#define NTAG  (E * T)

// ---------------- scratch ----------------
__device__ int   g_top_e[T * 2];   // per token: top-2 expert ids
__device__ float g_top_g[T * 2];   // per token: top-2 gate values
__device__ int   g_tok_row[T * 2]; // per token slot: destination row in (E*T)

// ---------------- kernel 1: fused zero-init + logits/softmax/top2 ----------------
// blocks [0,ZB): zero out_data, set tags=-1   (store/DRAM pipe)
// blocks [ZB,ZB+LB): logits in fp64, softmax, top-2   (DFMA pipe)
__global__ void k_fused(const float* __restrict__ x, const float* __restrict__ Wg,
                        float* __restrict__ out) {
    if (blockIdx.x < ZB) {
        // ----- zero data region + tag region (-1) as float4 -----
        const size_t N4d = DATA / 4;              // 16M float4 of 0
        const size_t N4  = N4d + NTAG / 4;        // + 8K float4 of -1
        float4* o4 = (float4*)out;
        const float4 z  = make_float4(0.f, 0.f, 0.f, 0.f);
        const float4 m1 = make_float4(-1.f, -1.f, -1.f, -1.f);
        const size_t stride = (size_t)ZB * 256;
        for (size_t i = blockIdx.x * 256 + threadIdx.x; i < N4; i += stride)
            o4[i] = (i < N4d) ? z : m1;
        return;
    }

    // ----- logits: warp w handles token (bid-ZB)*8+w -----
    __shared__ float sW[8][516];
    const int warp = threadIdx.x >> 5;
    const int lane = threadIdx.x & 31;
    const int t = (blockIdx.x - ZB) * 8 + warp;

    double acc[E];
#pragma unroll
    for (int e = 0; e < E; e++) acc[e] = 0.0;

    for (int c = 0; c < 4; c++) {
        __syncthreads();
        for (int i = threadIdx.x; i < 512 * 8; i += 256) {
            int d = i >> 3, e = i & 7;
            sW[e][d] = Wg[(c * 512 + d) * 8 + e];
        }
        __syncthreads();

        const float4* xr = (const float4*)(x + (size_t)t * D + c * 512);
#pragma unroll
        for (int i = 0; i < 4; i++) {
            float4 xv = xr[i * 32 + lane];
#pragma unroll
            for (int e = 0; e < E; e++) {
                float4 wv = *(const float4*)&sW[e][(i * 32 + lane) * 4];
                acc[e] += (double)xv.x * (double)wv.x;
                acc[e] += (double)xv.y * (double)wv.y;
                acc[e] += (double)xv.z * (double)wv.z;
                acc[e] += (double)xv.w * (double)wv.w;
            }
        }
    }

#pragma unroll
    for (int e = 0; e < E; e++) {
#pragma unroll
        for (int off = 16; off > 0; off >>= 1)
            acc[e] += __shfl_down_sync(0xffffffffu, acc[e], off);
    }

    if (lane == 0) {
        float lg[E];
#pragma unroll
        for (int e = 0; e < E; e++) lg[e] = (float)acc[e];

        float mx = lg[0];
#pragma unroll
        for (int e = 1; e < E; e++) mx = fmaxf(mx, lg[e]);
        float ex[E], sum = 0.f;
#pragma unroll
        for (int e = 0; e < E; e++) { ex[e] = __expf(lg[e] - mx); sum += ex[e]; }
        float inv = 1.0f / sum;

        // top-2, lowest index wins ties (matches jax.lax.top_k)
        int b0 = 0;
#pragma unroll
        for (int e = 1; e < E; e++) if (lg[e] > lg[b0]) b0 = e;
        int b1 = -1;
#pragma unroll
        for (int e = 0; e < E; e++) {
            if (e == b0) continue;
            if (b1 < 0 || lg[e] > lg[b1]) b1 = e;
        }
        g_top_e[t * 2 + 0] = b0;
        g_top_e[t * 2 + 1] = b1;
        g_top_g[t * 2 + 0] = ex[b0] * inv;
        g_top_g[t * 2 + 1] = ex[b1] * inv;
    }
}

// ---------------- kernel 2: ordered compaction -> token->row map ----------------
// single block, 512 threads, 8 contiguous tokens per thread (preserves order)
__global__ void k_route(float* __restrict__ out) {
    const int NT = 512, TPB = T / NT;  // 8
    const int tid = threadIdx.x;
    const int lane = tid & 31, wid = tid >> 5;  // 16 warps
    __shared__ int wsum[16];

    int e0[TPB], e1[TPB];
    const int t0 = tid * TPB;
#pragma unroll
    for (int j = 0; j < TPB; j++) {
        e0[j] = g_top_e[(t0 + j) * 2 + 0];
        e1[j] = g_top_e[(t0 + j) * 2 + 1];
    }
    __syncthreads();

    for (int e = 0; e < E; e++) {
        int cnt = 0;
#pragma unroll
        for (int j = 0; j < TPB; j++) cnt += (e0[j] == e) + (e1[j] == e);

        int incl = cnt;
#pragma unroll
        for (int off = 1; off < 32; off <<= 1) {
            int v = __shfl_up_sync(0xffffffffu, incl, off);
            if (lane >= off) incl += v;
        }
        if (lane == 31) wsum[wid] = incl;
        __syncthreads();
        if (tid < 32) {
            int v = (tid < 16) ? wsum[tid] : 0;
#pragma unroll
            for (int off = 1; off < 16; off <<= 1) {
                int u = __shfl_up_sync(0xffffffffu, v, off);
                if (lane >= off) v += u;
            }
            if (tid < 16) wsum[tid] = v;
        }
        __syncthreads();

        int wbase = wid ? wsum[wid - 1] : 0;
        int p = wbase + incl - cnt;
#pragma unroll
        for (int j = 0; j < TPB; j++) {
            if (e0[j] == e) {
                g_tok_row[(t0 + j) * 2 + 0] = e * T + p; p++;
            } else if (e1[j] == e) {
                g_tok_row[(t0 + j) * 2 + 1] = e * T + p; p++;
            }
        }
        if (tid == 0) out[DATA + NTAG + e] = (float)wsum[15];   // loads
        __syncthreads();
    }
}

// ---------------- kernel 3: scatter occupied rows + tags ----------------
// grid = T blocks; block t reads x[t] once, writes its 2 destination rows
__global__ void k_scatter(const float* __restrict__ x, float* __restrict__ out) {
    const int t = blockIdx.x;
    const int r0 = g_tok_row[t * 2 + 0];
    const int r1 = g_tok_row[t * 2 + 1];
    const float s0 = g_top_g[t * 2 + 0];
    const float s1 = g_top_g[t * 2 + 1];

    const float4* xr = (const float4*)(x + (size_t)t * D);
    float4* o0 = (float4*)(out + (size_t)r0 * D);
    float4* o1 = (float4*)(out + (size_t)r1 * D);
    const int i = threadIdx.x;   // 512 float4 per row, 2 per thread

    float4 a = xr[i], b = xr[i + 256];
    float4 a0 = make_float4(a.x * s0, a.y * s0, a.z * s0, a.w * s0);
    float4 b0 = make_float4(b.x * s0, b.y * s0, b.z * s0, b.w * s0);
    float4 a1 = make_float4(a.x * s1, a.y * s1, a.z * s1, a.w * s1);
    float4 b1 = make_float4(b.x * s1, b.y * s1, b.z * s1, b.w * s1);
    o0[i] = a0; o0[i + 256] = b0;
    o1[i] = a1; o1[i + 256] = b1;

    if (i == 0) out[DATA + r0] = (float)t;
    if (i == 1) out[DATA + r1] = (float)t;
}

// ---------------- launch ----------------
extern "C" void kernel_launch(void* const* d_in, const int* in_sizes, int n_in,
                              void* d_out, int out_size) {
    const float* x  = (const float*)d_in[0];
    const float* Wg = (const float*)d_in[1];
    float* out = (float*)d_out;

    k_fused<<<ZB + LB, 256>>>(x, Wg, out);
    k_route<<<1, 512>>>(out);
    k_scatter<<<T, 256>>>(x, out);
}